// round 14
// baseline (speedup 1.0000x reference)
#include <cuda_runtime.h>

#define B_ 16
#define C_ 512
#define N_ 4096
#define K_ 32

// 8 MB scratch for softmax weights w[b][n][k]
__device__ __align__(16) float g_w[B_ * N_ * K_];

typedef unsigned long long ull;

__device__ __forceinline__ ull pk2(float a, float b) {
    ull r; asm("mov.b64 %0, {%1, %2};" : "=l"(r) : "f"(a), "f"(b)); return r;
}
__device__ __forceinline__ void ffma2(ull &d, ull a, ull b) {
    asm("fma.rn.f32x2 %0, %1, %2, %0;" : "+l"(d) : "l"(a), "l"(b));
}
__device__ __forceinline__ void upk2(ull v, float &a, float &b) {
    asm("mov.b64 {%0, %1}, %2;" : "=f"(a), "=f"(b) : "l"(v));
}
__device__ __forceinline__ ull lds_u64(unsigned a) {
    ull v; asm volatile("ld.shared.b64 %0, [%1];" : "=l"(v) : "r"(a)); return v;
}
__device__ __forceinline__ float4 lds128(unsigned a) {
    float4 v;
    asm volatile("ld.shared.v4.f32 {%0,%1,%2,%3}, [%4];"
                 : "=f"(v.x), "=f"(v.y), "=f"(v.z), "=f"(v.w) : "r"(a));
    return v;
}

// ================= kernel 1: assign (xc gemm + softmax -> g_w, zeroes out) ==============
// 128 tokens/block, 256 threads = 8 warps (4 k-groups x 2 token-halves).
// DOUBLE-BUFFERED c-chunk staging: LDG for chunk i+1 overlaps compute of chunk i.
// smem words: xs buf0 [0,4096) | xs buf1 [4096,8192) | cw buf0 [8192,9344) |
//             cw buf1 [9344,10496) | sq [10496,11520) | sa [11520,11552) | sd [11552,11584)
#define AX0 0
#define AX1 4096
#define ACW0 8192
#define ACW1 9344
#define ASQ 10496
#define ASA 11520
#define ASD 11552
#define A_WORDS 11584

__global__ void __launch_bounds__(256) assign_kernel(const float *__restrict__ x,
                                                     const float *__restrict__ cw,
                                                     const float *__restrict__ scale,
                                                     float *__restrict__ out) {
    __shared__ __align__(16) float sm[A_WORDS];
    const int t = threadIdx.x;
    if (t < 128)
        reinterpret_cast<float4 *>(out)[blockIdx.x * 128 + t] = make_float4(0.f, 0.f, 0.f, 0.f);

    const int T0 = blockIdx.x * 128;
    const float *xb = x + (size_t)(T0 >> 12) * C_ * N_ + (T0 & (N_ - 1));
    const int L = t & 31, wmid = t >> 5, kg = wmid & 3, th = wmid >> 2;
    const int q = t & 31, kA = t >> 3, c4 = (t & 7) * 4;
    const unsigned smb = (unsigned)__cvta_generic_to_shared(sm);

    ull acc[8];
#pragma unroll
    for (int m = 0; m < 8; ++m) acc[m] = 0ull;
    float4 xsq4 = make_float4(0.f, 0.f, 0.f, 0.f);
    float csq = 0.f;

    float4 px[4], pc;
    // prologue: LDG chunk 0 (+ xsq/csq partials), STS -> buf0
#pragma unroll
    for (int j = 0; j < 4; ++j) {
        const int c = (t >> 5) + 8 * j;
        px[j] = *reinterpret_cast<const float4 *>(xb + (size_t)c * N_ + 4 * q);
        xsq4.x = fmaf(px[j].x, px[j].x, xsq4.x); xsq4.y = fmaf(px[j].y, px[j].y, xsq4.y);
        xsq4.z = fmaf(px[j].z, px[j].z, xsq4.z); xsq4.w = fmaf(px[j].w, px[j].w, xsq4.w);
    }
    pc = *reinterpret_cast<const float4 *>(cw + (size_t)kA * C_ + c4);
    csq = fmaf(pc.x, pc.x, csq); csq = fmaf(pc.y, pc.y, csq);
    csq = fmaf(pc.z, pc.z, csq); csq = fmaf(pc.w, pc.w, csq);
#pragma unroll
    for (int j = 0; j < 4; ++j)
        *reinterpret_cast<float4 *>(&sm[AX0 + ((t >> 5) + 8 * j) * 128 + 4 * q]) = px[j];
    sm[ACW0 + (c4 + 0) * 36 + kA] = pc.x;
    sm[ACW0 + (c4 + 1) * 36 + kA] = pc.y;
    sm[ACW0 + (c4 + 2) * 36 + kA] = pc.z;
    sm[ACW0 + (c4 + 3) * 36 + kA] = pc.w;
    __syncthreads();

#pragma unroll 1
    for (int ci = 0; ci < 16; ++ci) {
        if (ci < 15) {   // prefetch chunk ci+1 into regs (+ partials)
            const int cc = (ci + 1) * 32;
#pragma unroll
            for (int j = 0; j < 4; ++j) {
                const int c = (t >> 5) + 8 * j;
                px[j] = *reinterpret_cast<const float4 *>(xb + (size_t)(cc + c) * N_ + 4 * q);
                xsq4.x = fmaf(px[j].x, px[j].x, xsq4.x); xsq4.y = fmaf(px[j].y, px[j].y, xsq4.y);
                xsq4.z = fmaf(px[j].z, px[j].z, xsq4.z); xsq4.w = fmaf(px[j].w, px[j].w, xsq4.w);
            }
            pc = *reinterpret_cast<const float4 *>(cw + (size_t)kA * C_ + cc + c4);
            csq = fmaf(pc.x, pc.x, csq); csq = fmaf(pc.y, pc.y, csq);
            csq = fmaf(pc.z, pc.z, csq); csq = fmaf(pc.w, pc.w, csq);
        }
        // compute chunk ci from buf[ci&1]
        const unsigned xo = smb + (unsigned)((AX0 + (ci & 1) * 4096) * 4);
        const unsigned co = smb + (unsigned)((ACW0 + (ci & 1) * 1152) * 4);
#pragma unroll 4
        for (int c = 0; c < 32; ++c) {
            ull xp = lds_u64(xo + (unsigned)((c * 128 + 64 * th + 2 * L) * 4));
            float4 w0 = lds128(co + (unsigned)((c * 36 + 8 * kg) * 4));
            float4 w1 = lds128(co + (unsigned)((c * 36 + 8 * kg + 4) * 4));
            ffma2(acc[0], xp, pk2(w0.x, w0.x)); ffma2(acc[1], xp, pk2(w0.y, w0.y));
            ffma2(acc[2], xp, pk2(w0.z, w0.z)); ffma2(acc[3], xp, pk2(w0.w, w0.w));
            ffma2(acc[4], xp, pk2(w1.x, w1.x)); ffma2(acc[5], xp, pk2(w1.y, w1.y));
            ffma2(acc[6], xp, pk2(w1.z, w1.z)); ffma2(acc[7], xp, pk2(w1.w, w1.w));
        }
        if (ci < 15) {   // STS prefetched chunk -> other buffer
            const int nb = ((ci + 1) & 1);
#pragma unroll
            for (int j = 0; j < 4; ++j)
                *reinterpret_cast<float4 *>(&sm[AX0 + nb * 4096 + ((t >> 5) + 8 * j) * 128 + 4 * q]) = px[j];
            float *cd = &sm[ACW0 + nb * 1152];
            cd[(c4 + 0) * 36 + kA] = pc.x;
            cd[(c4 + 1) * 36 + kA] = pc.y;
            cd[(c4 + 2) * 36 + kA] = pc.z;
            cd[(c4 + 3) * 36 + kA] = pc.w;
        }
        __syncthreads();
    }

    // exchange xc -> sxc[tok][k] pitch 33 (region [0,4224) — mainloop done, safe)
    {
        const int tok = 64 * th + 2 * L;
#pragma unroll
        for (int kk = 0; kk < 8; ++kk) {
            float lo, hi;
            upk2(acc[kk], lo, hi);
            sm[tok * 33 + 8 * kg + kk] = lo;
            sm[(tok + 1) * 33 + 8 * kg + kk] = hi;
        }
    }
    *reinterpret_cast<float4 *>(&sm[ASQ + (t >> 5) * 128 + 4 * q]) = xsq4;
#pragma unroll
    for (int d = 1; d < 8; d <<= 1) csq += __shfl_xor_sync(0xffffffffu, csq, d);
    if ((t & 7) == 0) {
        float s = scale[kA];
        sm[ASA + kA] = s;
        sm[ASD + kA] = s * csq;
    }
    __syncthreads();

    if (t < 128) {
        float xsq = 0.f;
#pragma unroll
        for (int r = 0; r < 8; ++r) xsq += sm[ASQ + r * 128 + t];
        float l[K_];
        float mx = -1e30f;
#pragma unroll
        for (int k = 0; k < K_; ++k) {
            float lv = sm[ASA + k] * (xsq - 2.0f * sm[t * 33 + k]) + sm[ASD + k];
            l[k] = lv; mx = fmaxf(mx, lv);
        }
        float s = 0.f;
#pragma unroll
        for (int k = 0; k < K_; ++k) { float e = __expf(l[k] - mx); l[k] = e; s += e; }
        float inv = 1.0f / s;
#pragma unroll
        for (int k = 0; k < K_; ++k) sm[t * 33 + k] = l[k] * inv;
    }
    __syncthreads();

    float *gw = g_w + (size_t)T0 * K_;
#pragma unroll
    for (int i = 0; i < 16; ++i) {
        const int f = t + 256 * i;
        gw[f] = sm[(f >> 5) * 33 + (f & 31)];
    }
}

// ================= kernel 2: aggregate (enc gemm, double-buffered staging) ==============
// grid (16 n-splits, 16 b, 2 c-tiles), 256 threads = 8 warps (4 k-groups x 2 c-halves).
// dyn smem words: ws[256][32]=8192 | xs buf0 [8192,12320) | xs buf1 [12320,16448) |
//                 wpart [16448,17472) | wsf [17472,17504)
#define WS0 0
#define GX0 8192
#define GX1 12320
#define WP0 16448
#define WF0 17472
#define AGG_WORDS 17504
#define XP 258

__global__ void __launch_bounds__(256) aggregate_kernel(const float *__restrict__ x,
                                                        const float *__restrict__ cw,
                                                        float *__restrict__ out) {
    extern __shared__ float sg[];
    const int t = threadIdx.x;
    const int b = blockIdx.y;
    const int n0 = blockIdx.x * 256;
    const int cbase = blockIdx.z * 256;
    const int L = t & 31, wmid = t >> 5, kg = wmid & 3, ch = wmid >> 2;
    const unsigned smb = (unsigned)__cvta_generic_to_shared(sg);
    const float *xg = x + ((size_t)b * C_ + cbase) * N_ + n0;

    // stage w chunk [256 n][32 k] + wsum partials
    {
        const float4 *gw4 = reinterpret_cast<const float4 *>(g_w + ((size_t)b * N_ + n0) * K_);
        float4 wsum4 = make_float4(0.f, 0.f, 0.f, 0.f);
#pragma unroll
        for (int j = 0; j < 8; ++j) {
            const int flat = t + 256 * j;
            float4 v = gw4[flat];
            *reinterpret_cast<float4 *>(&sg[WS0 + 4 * flat]) = v;
            wsum4.x += v.x; wsum4.y += v.y; wsum4.z += v.z; wsum4.w += v.w;
        }
        *reinterpret_cast<float4 *>(&sg[WP0 + 4 * t]) = wsum4;
    }

    ull acc[16];
#pragma unroll
    for (int m = 0; m < 16; ++m) acc[m] = 0ull;

    float4 pv[4];
    // prologue: LDG stage 0, STS transposed -> buf0
#pragma unroll
    for (int j = 0; j < 4; ++j) {
        const int flat = t + 256 * j;
        pv[j] = *reinterpret_cast<const float4 *>(xg + (size_t)(flat >> 2) * N_ + 4 * (flat & 3));
    }
#pragma unroll
    for (int j = 0; j < 4; ++j) {
        const int flat = t + 256 * j, c = flat >> 2, qq = flat & 3;
        sg[GX0 + (4 * qq + 0) * XP + c] = pv[j].x;
        sg[GX0 + (4 * qq + 1) * XP + c] = pv[j].y;
        sg[GX0 + (4 * qq + 2) * XP + c] = pv[j].z;
        sg[GX0 + (4 * qq + 3) * XP + c] = pv[j].w;
    }
    __syncthreads();

#pragma unroll 1
    for (int s = 0; s < 16; ++s) {
        if (s < 15) {   // prefetch stage s+1
#pragma unroll
            for (int j = 0; j < 4; ++j) {
                const int flat = t + 256 * j;
                pv[j] = *reinterpret_cast<const float4 *>(
                    xg + (size_t)(flat >> 2) * N_ + (s + 1) * 16 + 4 * (flat & 3));
            }
        }
        // compute stage s from buf[s&1]
        const unsigned xo = smb + (unsigned)((GX0 + (s & 1) * 4128) * 4);
#pragma unroll 4
        for (int nn = 0; nn < 16; ++nn) {
            const int n = s * 16 + nn;
            ull xp0 = lds_u64(xo + (unsigned)((nn * XP + 128 * ch + 2 * L) * 4));
            ull xp1 = lds_u64(xo + (unsigned)((nn * XP + 128 * ch + 64 + 2 * L) * 4));
            float4 w0 = lds128(smb + (unsigned)((WS0 + n * 32 + 8 * kg) * 4));
            float4 w1 = lds128(smb + (unsigned)((WS0 + n * 32 + 8 * kg + 4) * 4));
            ull wv[8] = {pk2(w0.x, w0.x), pk2(w0.y, w0.y), pk2(w0.z, w0.z), pk2(w0.w, w0.w),
                         pk2(w1.x, w1.x), pk2(w1.y, w1.y), pk2(w1.z, w1.z), pk2(w1.w, w1.w)};
#pragma unroll
            for (int kk = 0; kk < 8; ++kk) {
                ffma2(acc[kk], xp0, wv[kk]);
                ffma2(acc[8 + kk], xp1, wv[kk]);
            }
        }
        if (s < 15) {   // STS prefetched stage -> other buffer
            float *xd = &sg[GX0 + ((s + 1) & 1) * 4128];
#pragma unroll
            for (int j = 0; j < 4; ++j) {
                const int flat = t + 256 * j, c = flat >> 2, qq = flat & 3;
                xd[(4 * qq + 0) * XP + c] = pv[j].x;
                xd[(4 * qq + 1) * XP + c] = pv[j].y;
                xd[(4 * qq + 2) * XP + c] = pv[j].z;
                xd[(4 * qq + 3) * XP + c] = pv[j].w;
            }
        }
        __syncthreads();
    }

    // reduce wsum partials (32 per k-quad)
    if (t < 8) {
        float4 s4 = make_float4(0.f, 0.f, 0.f, 0.f);
#pragma unroll
        for (int j = 0; j < 32; ++j) {
            float4 v = *reinterpret_cast<const float4 *>(&sg[WP0 + 4 * (t + 8 * j)]);
            s4.x += v.x; s4.y += v.y; s4.z += v.z; s4.w += v.w;
        }
        *reinterpret_cast<float4 *>(&sg[WF0 + 4 * t]) = s4;
    }
    __syncthreads();

    // epilogue: fold -wsum*cw, REDG to out
    float *ob = out + (size_t)b * K_ * C_;
#pragma unroll
    for (int kk = 0; kk < 8; ++kk) {
        const int k = 8 * kg + kk;
        const float wk = sg[WF0 + k];
#pragma unroll
        for (int j = 0; j < 2; ++j) {
            const int c = cbase + 128 * ch + 64 * j + 2 * L;
            float a0, a1;
            upk2(acc[j * 8 + kk], a0, a1);
            float2 cv = *reinterpret_cast<const float2 *>(&cw[(size_t)k * C_ + c]);
            atomicAdd(&ob[(size_t)k * C_ + c], a0 - wk * cv.x);
            atomicAdd(&ob[(size_t)k * C_ + c + 1], a1 - wk * cv.y);
        }
    }
}

extern "C" void kernel_launch(void *const *d_in, const int *in_sizes, int n_in,
                              void *d_out, int out_size) {
    const float *x = (const float *)d_in[0];
    const float *cwp = (const float *)d_in[1];
    const float *scale = (const float *)d_in[2];
    float *out = (float *)d_out;

    cudaFuncSetAttribute(aggregate_kernel, cudaFuncAttributeMaxDynamicSharedMemorySize,
                         AGG_WORDS * (int)sizeof(float));

    assign_kernel<<<(B_ * N_) / 128, 256>>>(x, cwp, scale, out);
    aggregate_kernel<<<dim3(N_ / 256, B_, 2), 256, AGG_WORDS * sizeof(float)>>>(x, cwp, out);
}